// round 9
// baseline (speedup 1.0000x reference)
#include <cuda_runtime.h>
#include <math.h>

// SpatialGradient: depthwise 3x3 Sobel, zero SAME padding, [B,C,H,W]=[8,32,512,512] fp32.
// direction<0 -> |gx| ; direction>0 -> |gy| ; direction==0 -> sqrt(gx^2+gy^2).
// Thread computes an 8-wide x 8-row output patch with a 3-row register sliding window.
// Separable Sobel: per-column vertical smooth (t) / diff (d), then cheap horizontal pass.
// sqrt via PTX sqrt.approx.f32 (rel err ~1e-7 << 1e-3 tolerance).
// Warp = 32 threads covering 256 contiguous columns of one row -> horizontal halo
// exchanged via warp shuffle (only edge lanes touch memory for halo).
// Output written with streaming (.cs) stores: write-once data, keep L2 for input reuse.
// Block 32x8 covers a 256-col x 64-row tile.

#define H_DIM 512
#define W_DIM 512
#define ROWS_PER_THREAD 8

__device__ int g_zero_dir = 0;   // fallback if direction input is absent

__device__ __forceinline__ float sqrt_approx(float x) {
    float y;
    asm("sqrt.approx.f32 %0, %1;" : "=f"(y) : "f"(x));
    return y;
}

__device__ __forceinline__ void load_row(const float* __restrict__ p,
                                         int yy, int x0, float r[10])
{
    float4 c0, c1;
    const bool valid = (yy >= 0) && (yy < H_DIM);   // warp-uniform
    if (valid) {
        const float* row = p + yy * W_DIM + x0;
        c0 = *(const float4*)row;          // x0 is 32B-aligned
        c1 = *(const float4*)(row + 4);
    } else {
        c0 = make_float4(0.f, 0.f, 0.f, 0.f);
        c1 = c0;
    }
    r[1] = c0.x; r[2] = c0.y; r[3] = c0.z; r[4] = c0.w;
    r[5] = c1.x; r[6] = c1.y; r[7] = c1.z; r[8] = c1.w;

    // Horizontal halo from neighbor lanes (warp-uniform yy, full mask).
    float left  = __shfl_up_sync(0xffffffffu, r[8], 1);   // lane i-1's col x0-1
    float right = __shfl_down_sync(0xffffffffu, r[1], 1); // lane i+1's col x0+8

    const int lane = threadIdx.x;
    if (lane == 0)
        left  = (valid && x0 > 0)          ? __ldg(p + yy * W_DIM + x0 - 1) : 0.0f;
    if (lane == 31)
        right = (valid && x0 + 8 < W_DIM)  ? __ldg(p + yy * W_DIM + x0 + 8) : 0.0f;

    r[0] = left;
    r[9] = right;
}

__global__ __launch_bounds__(256) void sobel_kernel(
    const float* __restrict__ in,
    const int*   __restrict__ dir_p,
    float*       __restrict__ out)
{
    const int tx = threadIdx.x;                              // 0..31 (one warp per row)
    const int ty = threadIdx.y;                              // 0..7
    const int x0 = blockIdx.x * 256 + tx * 8;                // first output column
    const int y0 = (blockIdx.y * 8 + ty) * ROWS_PER_THREAD;  // first output row
    const long long img = blockIdx.z;

    const float* p = in  + img * (long long)(H_DIM * W_DIM);
    float*       q = out + img * (long long)(H_DIM * W_DIM);

    const int dir = *dir_p;  // uniform broadcast

    float a[10], b[10], c[10];    // rows y-1, y, y+1 (rolling)
    load_row(p, y0 - 1, x0, a);
    load_row(p, y0,     x0, b);

    #pragma unroll
    for (int rr = 0; rr < ROWS_PER_THREAD; rr++) {
        const int y = y0 + rr;
        load_row(p, y + 1, x0, c);

        // Separable vertical pass: smooth (for gx) and diff (for gy), per column.
        float t[10], d[10];
        #pragma unroll
        for (int k = 0; k < 10; k++) {
            t[k] = fmaf(2.0f, b[k], a[k]) + c[k];   // a + 2b + c
            d[k] = c[k] - a[k];                     // c - a
        }

        float res[8];
        #pragma unroll
        for (int j = 0; j < 8; j++) {
            const float gx = t[j+2] - t[j];
            const float gy = fmaf(2.0f, d[j+1], d[j]) + d[j+2];
            float v;
            if (dir < 0)      v = fabsf(gx);
            else if (dir > 0) v = fabsf(gy);
            else              v = sqrt_approx(fmaf(gx, gx, gy * gy));
            res[j] = v;
        }

        float* qrow = q + y * W_DIM + x0;
        __stcs((float4*)qrow,       make_float4(res[0], res[1], res[2], res[3]));
        __stcs((float4*)(qrow + 4), make_float4(res[4], res[5], res[6], res[7]));

        // rotate window: a <- b, b <- c (renamed away by ptxas after full unroll)
        #pragma unroll
        for (int j = 0; j < 10; j++) { a[j] = b[j]; b[j] = c[j]; }
    }
}

extern "C" void kernel_launch(void* const* d_in, const int* in_sizes, int n_in,
                              void* d_out, int out_size)
{
    const float* input = (const float*)d_in[0];
    float*       outp  = (float*)d_out;

    const int* dir;
    if (n_in >= 2) {
        dir = (const int*)d_in[1];
    } else {
        // Defensive fallback: direction=0 (the setup_inputs default).
        int* dz;
        cudaGetSymbolAddress((void**)&dz, g_zero_dir);
        dir = dz;
    }

    const int n_imgs = in_sizes[0] / (H_DIM * W_DIM);   // B*C = 256

    dim3 block(32, 8, 1);
    dim3 grid(W_DIM / 256, H_DIM / (8 * ROWS_PER_THREAD), n_imgs);  // (2, 8, 256)
    sobel_kernel<<<grid, block>>>(input, dir, outp);
}

// round 12
// speedup vs baseline: 1.1167x; 1.1167x over previous
#include <cuda_runtime.h>
#include <math.h>

// SpatialGradient: depthwise 3x3 Sobel, zero SAME padding, [B,C,H,W]=[8,32,512,512] fp32.
// direction<0 -> |gx| ; direction>0 -> |gy| ; direction==0 -> sqrt(gx^2+gy^2).
// 8-wide x 8-row per thread, 3-row register sliding window, software-pipelined row
// prefetch (distance 1) to keep 2 row-segments of LDGs in flight per warp.
// Warp covers 256 contiguous columns of one row; horizontal halo via warp shuffle.
// Streaming (.cs) output stores. Block 32x8 covers a 256x64 tile.

#define H_DIM 512
#define W_DIM 512
#define ROWS_PER_THREAD 8

__device__ int g_zero_dir = 0;   // fallback if direction input is absent

__device__ __forceinline__ float sqrt_approx(float x) {
    float y;
    asm("sqrt.approx.f32 %0, %1;" : "=f"(y) : "f"(x));
    return y;
}

struct Pre {
    float4 c0, c1;
    float  edge;    // left halo for lane 0, right halo for lane 31
};

// Issue the loads for one row-segment (no dependent ops -> LDGs go in flight).
__device__ __forceinline__ Pre fetch_row(const float* __restrict__ p,
                                         int yy, int x0, int lane)
{
    Pre f;
    const bool valid = (yy >= 0) && (yy < H_DIM);   // warp-uniform
    f.edge = 0.0f;
    if (valid) {
        const float* row = p + yy * W_DIM + x0;
        f.c0 = *(const float4*)row;          // x0 is 32B-aligned
        f.c1 = *(const float4*)(row + 4);
        if (lane == 0  && x0 > 0)          f.edge = __ldg(row - 1);
        if (lane == 31 && x0 + 8 < W_DIM)  f.edge = __ldg(row + 8);
    } else {
        f.c0 = make_float4(0.f, 0.f, 0.f, 0.f);
        f.c1 = f.c0;
    }
    return f;
}

// Consume a fetched row: unpack + exchange horizontal halo via shuffle.
__device__ __forceinline__ void finish_row(const Pre& f, int lane, float r[10])
{
    r[1] = f.c0.x; r[2] = f.c0.y; r[3] = f.c0.z; r[4] = f.c0.w;
    r[5] = f.c1.x; r[6] = f.c1.y; r[7] = f.c1.z; r[8] = f.c1.w;

    float left  = __shfl_up_sync(0xffffffffu, r[8], 1);   // lane i-1's col x0-1
    float right = __shfl_down_sync(0xffffffffu, r[1], 1); // lane i+1's col x0+8
    if (lane == 0)  left  = f.edge;
    if (lane == 31) right = f.edge;
    r[0] = left;
    r[9] = right;
}

__global__ __launch_bounds__(256, 4) void sobel_kernel(
    const float* __restrict__ in,
    const int*   __restrict__ dir_p,
    float*       __restrict__ out)
{
    const int lane = threadIdx.x;                            // 0..31 (one warp per row)
    const int ty   = threadIdx.y;                            // 0..7
    const int x0 = blockIdx.x * 256 + lane * 8;              // first output column
    const int y0 = (blockIdx.y * 8 + ty) * ROWS_PER_THREAD;  // first output row
    const long long img = blockIdx.z;

    const float* p = in  + img * (long long)(H_DIM * W_DIM);
    float*       q = out + img * (long long)(H_DIM * W_DIM);

    const int dir = *dir_p;  // uniform broadcast

    float a[10], b[10], c[10];    // rows y-1, y, y+1 (rolling)
    {
        Pre fa = fetch_row(p, y0 - 1, x0, lane);
        Pre fb = fetch_row(p, y0,     x0, lane);
        finish_row(fa, lane, a);
        finish_row(fb, lane, b);
    }
    Pre f = fetch_row(p, y0 + 1, x0, lane);   // row y0+1 in flight

    #pragma unroll
    for (int rr = 0; rr < ROWS_PER_THREAD; rr++) {
        const int y = y0 + rr;

        // Prefetch row y+2 (statically elided on the last iteration).
        Pre fn;
        if (rr < ROWS_PER_THREAD - 1)
            fn = fetch_row(p, y + 2, x0, lane);

        finish_row(f, lane, c);   // waits on row y+1's loads

        // Separable vertical pass: smooth (for gx) and diff (for gy), per column.
        float t[10], d[10];
        #pragma unroll
        for (int k = 0; k < 10; k++) {
            t[k] = fmaf(2.0f, b[k], a[k]) + c[k];   // a + 2b + c
            d[k] = c[k] - a[k];                     // c - a
        }

        float res[8];
        #pragma unroll
        for (int j = 0; j < 8; j++) {
            const float gx = t[j+2] - t[j];
            const float gy = fmaf(2.0f, d[j+1], d[j]) + d[j+2];
            float v;
            if (dir < 0)      v = fabsf(gx);
            else if (dir > 0) v = fabsf(gy);
            else              v = sqrt_approx(fmaf(gx, gx, gy * gy));
            res[j] = v;
        }

        float* qrow = q + y * W_DIM + x0;
        __stcs((float4*)qrow,       make_float4(res[0], res[1], res[2], res[3]));
        __stcs((float4*)(qrow + 4), make_float4(res[4], res[5], res[6], res[7]));

        // rotate window: a <- b, b <- c (renamed away by ptxas after full unroll)
        #pragma unroll
        for (int j = 0; j < 10; j++) { a[j] = b[j]; b[j] = c[j]; }

        if (rr < ROWS_PER_THREAD - 1)
            f = fn;
    }
}

extern "C" void kernel_launch(void* const* d_in, const int* in_sizes, int n_in,
                              void* d_out, int out_size)
{
    const float* input = (const float*)d_in[0];
    float*       outp  = (float*)d_out;

    const int* dir;
    if (n_in >= 2) {
        dir = (const int*)d_in[1];
    } else {
        int* dz;
        cudaGetSymbolAddress((void**)&dz, g_zero_dir);
        dir = dz;
    }

    const int n_imgs = in_sizes[0] / (H_DIM * W_DIM);   // B*C = 256

    dim3 block(32, 8, 1);
    dim3 grid(W_DIM / 256, H_DIM / (8 * ROWS_PER_THREAD), n_imgs);  // (2, 8, 256)
    sobel_kernel<<<grid, block>>>(input, dir, outp);
}